// round 14
// baseline (speedup 1.0000x reference)
#include <cuda_runtime.h>
#include <cuda_fp16.h>
#include <cstdint>

// ---------------------------------------------------------------------------
// GeneralizedRCNNExtractModel via HMMA (mma.sync f16) GEMMs.
//   f6     = relu(x @ W6 + b6)            2000x12544 @ 12544x1024
//   f7     = relu(f6 @ W7 + b7)           2000x1024  @ 1024x1024
//   logits = f7 @ [Wcls|Wbox] + bias      2000x1024 @ 1024x405 (pad 512)
// R14: 1-pass fp16 GEMM (R12 structure, chunk 32) with 256-thread CTAs of
// 8 warps (32x64 tiles, R7 mapping) at 2 CTAs/SM -> 16 warps/SM. R12's
// tensor=39.7% at 8 warps/SM is ldsm-latency exposure, not bandwidth;
// doubling resident warps covers it (R7 evidence: 16 warps sustained 54%).
// ---------------------------------------------------------------------------

#define NUM_CLASSES 81
#define SCORE_THRESH 0.05f
#define BBOX_XFORM_CLIP 4.135166556742356f

#define RMAX 2000
#define KDIM 12544
#define HDIM 1024
#define NHEAD 512   // 405 used, padded

// --------------------------- device scratch -------------------------------
__device__ __half g_xh[RMAX * KDIM];     // fp16 x
__device__ __half g_w6h[HDIM * KDIM];    // W6^T fp16 [N][K]
__device__ __half g_w7h[HDIM * HDIM];    // W7^T fp16
__device__ __half g_whh[NHEAD * HDIM];   // [Wcls|Wbox]^T; rows 405..511 zero
__device__ __half g_f6h[RMAX * HDIM];
__device__ __half g_f7h[RMAX * HDIM];
__device__ float  g_part[2 * RMAX * HDIM];   // split-K partials

// --------------------------- PTX helpers ----------------------------------
__device__ __forceinline__ uint32_t smem_to_u32(const void* p) {
    uint32_t a;
    asm("{ .reg .u64 t; cvta.to.shared.u64 t, %1; cvt.u32.u64 %0, t; }"
        : "=r"(a) : "l"(p));
    return a;
}
__device__ __forceinline__ void cp_async16(uint32_t dst, const void* src, bool pred) {
    int sz = pred ? 16 : 0;
    asm volatile("cp.async.cg.shared.global [%0], [%1], 16, %2;"
                 :: "r"(dst), "l"(src), "r"(sz) : "memory");
}
#define CP_COMMIT() asm volatile("cp.async.commit_group;" ::: "memory")
#define CP_WAIT(N)  asm volatile("cp.async.wait_group %0;" :: "n"(N) : "memory")

__device__ __forceinline__ void ldsm_x4(uint32_t& r0, uint32_t& r1,
                                        uint32_t& r2, uint32_t& r3, uint32_t addr) {
    asm volatile("ldmatrix.sync.aligned.m8n8.x4.shared.b16 {%0,%1,%2,%3}, [%4];"
                 : "=r"(r0), "=r"(r1), "=r"(r2), "=r"(r3) : "r"(addr));
}
__device__ __forceinline__ void mma16816h(float* c, const uint32_t* a,
                                          uint32_t b0, uint32_t b1) {
    asm volatile(
        "mma.sync.aligned.m16n8k16.row.col.f32.f16.f16.f32 "
        "{%0,%1,%2,%3}, {%4,%5,%6,%7}, {%8,%9}, {%0,%1,%2,%3};"
        : "+f"(c[0]), "+f"(c[1]), "+f"(c[2]), "+f"(c[3])
        : "r"(a[0]), "r"(a[1]), "r"(a[2]), "r"(a[3]), "r"(b0), "r"(b1));
}

// swizzled smem offset for (row, 16B-chunk), 64B logical rows.
__device__ __forceinline__ uint32_t swoff(int row, int chunk) {
    return (uint32_t)(row * 64 + ((chunk ^ ((row >> 1) & 3)) << 4));
}

// --------------------------- mega prep kernel -----------------------------
#define NBX 1024

__device__ void transpose_half_job(const float* __restrict__ W, int K, int Nsrc,
                                   int ldT, int rowoff,
                                   __half* __restrict__ Th, int lb, int tid) {
    __shared__ float t[32][33];
    const int ntn = (Nsrc + 31) / 32;
    const int n0 = (lb % ntn) * 32;
    const int k0 = (lb / ntn) * 32;
    const int tx = tid & 31, ty = tid >> 5;  // 32 x 8
#pragma unroll
    for (int i = 0; i < 32; i += 8) {
        float v = 0.f;
        if (n0 + tx < Nsrc)
            v = W[(size_t)(k0 + ty + i) * Nsrc + n0 + tx];
        t[ty + i][tx] = v;
    }
    __syncthreads();
#pragma unroll
    for (int i = 0; i < 32; i += 8) {
        const int n = n0 + ty + i;
        if (n >= Nsrc) continue;
        Th[(size_t)(rowoff + n) * ldT + k0 + tx] = __float2half(t[tx][ty + i]);
    }
}

__global__ __launch_bounds__(256)
void prep_kernel(const float* __restrict__ x,
                 const float* __restrict__ W6,
                 const float* __restrict__ W7,
                 const float* __restrict__ Wcls,
                 const float* __restrict__ Wbox,
                 __half* __restrict__ xh,
                 __half* __restrict__ w6h,
                 __half* __restrict__ w7h,
                 __half* __restrict__ whh,
                 int M, int K1, int H, int NC) {
    const int tid = threadIdx.x;
    const int nbW6 = (H / 32) * (K1 / 32);
    const int nbW7 = (H / 32) * (H / 32);
    const int nbWc = ((NC + 31) / 32) * (H / 32);
    const int nbWb = ((NC * 4 + 31) / 32) * (H / 32);
    int b = blockIdx.x;

    if (b < NBX) {
        const size_t n4 = ((size_t)M * K1) / 4;
        size_t i = (size_t)b * 256 + tid;
        const size_t stride = (size_t)NBX * 256;
        const float4* X4 = reinterpret_cast<const float4*>(x);
        __half2* H2 = reinterpret_cast<__half2*>(xh);
        for (; i < n4; i += stride) {
            float4 v = X4[i];
            H2[i * 2 + 0] = __half2(__float2half(v.x), __float2half(v.y));
            H2[i * 2 + 1] = __half2(__float2half(v.z), __float2half(v.w));
        }
        return;
    }
    b -= NBX;
    if (b < nbW6) { transpose_half_job(W6, K1, H, K1, 0, w6h, b, tid); return; }
    b -= nbW6;
    if (b < nbW7) { transpose_half_job(W7, H, H, H, 0, w7h, b, tid); return; }
    b -= nbW7;
    if (b < nbWc) { transpose_half_job(Wcls, H, NC, H, 0, whh, b, tid); return; }
    b -= nbWc;
    if (b < nbWb) { transpose_half_job(Wbox, H, NC * 4, H, NC, whh, b, tid); return; }
}

// --------------------------- fp16 1-pass GEMM (split-K) -------------------
// Partial[z][M][N] = sum over K-slice z of A@B^T (pure fp16, f32 accum).
// Block 128x128, 8 warps of 32x64 (2x4 warp grid). Stage = A 8K | B 8K,
// 3-stage cp.async pipeline (48KB smem), 2 CTAs/SM = 16 warps/SM.
// Ksl%32==0, N%128==0.
__global__ __launch_bounds__(256, 2)
void hmma_gemm_f16(int M, int N, int K, int Ksl,
                   const __half* __restrict__ A,
                   const __half* __restrict__ B,
                   float* __restrict__ Pout) {
    extern __shared__ char smem[];
    const uint32_t sbase = smem_to_u32(smem);
    const int tid = threadIdx.x, lane = tid & 31, wid = tid >> 5;
    const int bm = blockIdx.y * 128, bn = blockIdx.x * 128;
    const int wm = (wid & 3) * 32, wn = (wid >> 2) * 64;
    const int kbase = blockIdx.z * Ksl;

    constexpr uint32_t STAGE = 16384u;   // A 8K | B 8K
    constexpr int NSTAGE = 3;

    // ---- cp.async per-thread addressing: 512 slots, 256 thr x 2 iters ----
    uint32_t offT[2];
    size_t gofA[2], gofB[2];
    bool predA[2];
#pragma unroll
    for (int i = 0; i < 2; ++i) {
        const int idx = tid + i * 256;           // 0..511
        const int row = idx >> 2, ch = idx & 3;  // 128 rows x 4 chunks(16B)
        offT[i] = swoff(row, ch);
        const int ra = (bm + row < M) ? (bm + row) : (M - 1);
        predA[i] = (bm + row < M);
        gofA[i] = (size_t)ra * K + kbase + ch * 8;
        gofB[i] = (size_t)(bn + row) * K + kbase + ch * 8;
    }

    // ---- ldmatrix fragment offsets ----
    uint32_t aFrag[2][2];  // [mt][kc]
#pragma unroll
    for (int mt = 0; mt < 2; ++mt) {
        const int row = wm + mt * 16 + (lane & 15);
#pragma unroll
        for (int kc = 0; kc < 2; ++kc)
            aFrag[mt][kc] = swoff(row, (lane >> 4) + kc * 2);
    }
    uint32_t bFrag[4][2];  // [nt][kc]
#pragma unroll
    for (int nt = 0; nt < 4; ++nt) {
        const int row = wn + nt * 16 + ((lane & 7) | ((lane >> 4) << 3));
#pragma unroll
        for (int kc = 0; kc < 2; ++kc)
            bFrag[nt][kc] = swoff(row, ((lane >> 3) & 1) + kc * 2);
    }

    float acc[2][8][4];   // 64 regs
#pragma unroll
    for (int mt = 0; mt < 2; ++mt)
#pragma unroll
        for (int nf = 0; nf < 8; ++nf)
#pragma unroll
            for (int k = 0; k < 4; ++k) acc[mt][nf][k] = 0.f;

    const int S = Ksl / 32;

    auto issue = [&](int step) {
        const size_t k0 = (size_t)step * 32;
        const uint32_t st = (uint32_t)(step % NSTAGE) * STAGE;
#pragma unroll
        for (int i = 0; i < 2; ++i) {
            cp_async16(sbase + st + offT[i],        A + gofA[i] + k0, predA[i]);
            cp_async16(sbase + st + 8192 + offT[i], B + gofB[i] + k0, true);
        }
        CP_COMMIT();
    };

    issue(0);
    if (S > 1) issue(1);

#pragma unroll 1
    for (int s = 0; s < S; ++s) {
        if (s + 1 < S) { CP_WAIT(1); } else { CP_WAIT(0); }
        __syncthreads();
        if (s + 2 < S) issue(s + 2);

        const uint32_t baseA = sbase + (uint32_t)(s % NSTAGE) * STAGE;
        const uint32_t baseB = baseA + 8192u;
#pragma unroll
        for (int kc = 0; kc < 2; ++kc) {
            uint32_t a[2][4];
            ldsm_x4(a[0][0], a[0][1], a[0][2], a[0][3], baseA + aFrag[0][kc]);
            ldsm_x4(a[1][0], a[1][1], a[1][2], a[1][3], baseA + aFrag[1][kc]);
#pragma unroll
            for (int nt = 0; nt < 4; ++nt) {
                uint32_t b0, b1, b2, b3;
                ldsm_x4(b0, b1, b2, b3, baseB + bFrag[nt][kc]);
                mma16816h(acc[0][nt * 2 + 0], a[0], b0, b1);
                mma16816h(acc[0][nt * 2 + 1], a[0], b2, b3);
                mma16816h(acc[1][nt * 2 + 0], a[1], b0, b1);
                mma16816h(acc[1][nt * 2 + 1], a[1], b2, b3);
            }
        }
    }

    float* P = Pout + (size_t)blockIdx.z * M * N;
#pragma unroll
    for (int mt = 0; mt < 2; ++mt) {
#pragma unroll
        for (int nf = 0; nf < 8; ++nf) {
            const int col = bn + wn + nf * 8 + (lane & 3) * 2;
#pragma unroll
            for (int half = 0; half < 2; ++half) {
                const int row = bm + wm + mt * 16 + (lane >> 2) + half * 8;
                if (row >= M) continue;
                *reinterpret_cast<float2*>(&P[(size_t)row * N + col]) =
                    make_float2(acc[mt][nf][half * 2 + 0],
                                acc[mt][nf][half * 2 + 1]);
            }
        }
    }
}

// --------------------------- split-K reduce + epilogue --------------------
__global__ __launch_bounds__(256)
void reduce_epilogue(int M, int N,
                     const float* __restrict__ P,
                     const float* __restrict__ bias, int do_relu,
                     float* __restrict__ C, int ldc,
                     __half* __restrict__ Oh, int ldo) {
    const size_t i = (size_t)blockIdx.x * blockDim.x + threadIdx.x;
    const size_t n2 = (size_t)M * N / 2;
    if (i >= n2) return;
    const float2 p0 = reinterpret_cast<const float2*>(P)[i];
    const float2 p1 = reinterpret_cast<const float2*>(P + (size_t)M * N)[i];
    const int col = (int)((i * 2) % N);
    const int row = (int)((i * 2) / N);
    float v0 = p0.x + p1.x + bias[col];
    float v1 = p0.y + p1.y + bias[col + 1];
    if (do_relu) { v0 = fmaxf(v0, 0.f); v1 = fmaxf(v1, 0.f); }
    if (C)
        *reinterpret_cast<float2*>(&C[(size_t)row * ldc + col]) =
            make_float2(v0, v1);
    if (Oh)
        *reinterpret_cast<__half2*>(&Oh[(size_t)row * ldo + col]) =
            __half2(__float2half(v0), __float2half(v1));
}

// --------------------------- postprocess (+head reduce) -------------------
__global__ __launch_bounds__(128)
void postprocess_kernel(int M,
                        const float* __restrict__ P,   // [2][M][NHEAD]
                        const float* __restrict__ bcls,
                        const float* __restrict__ bbox_b,
                        const float* __restrict__ boxes,
                        float* __restrict__ out, int ldo) {
    const int r = blockIdx.x;
    const int t = threadIdx.x;
    __shared__ float sl[NUM_CLASSES * 5];  // 405
    __shared__ float smax, ssum;

    const float* p0 = P + (size_t)r * NHEAD;
    const float* p1 = P + (size_t)M * NHEAD + (size_t)r * NHEAD;
    for (int i = t; i < NUM_CLASSES * 5; i += 128) {
        const float bias = (i < NUM_CLASSES) ? bcls[i] : bbox_b[i - NUM_CLASSES];
        sl[i] = p0[i] + p1[i] + bias;
    }
    __syncthreads();

    if (t == 0) {
        float m = -1e30f;
        for (int i = 0; i < NUM_CLASSES; ++i) m = fmaxf(m, sl[i]);
        float s = 0.f;
        for (int i = 0; i < NUM_CLASSES; ++i) s += expf(sl[i] - m);
        smax = m;
        ssum = s;
    }
    __syncthreads();

    if (t < NUM_CLASSES - 1) {
        const int j = t + 1;
        const float p = expf(sl[j] - smax) / ssum;
        const bool keep = p > SCORE_THRESH;

        const float bx0 = boxes[r * 4 + 0];
        const float by0 = boxes[r * 4 + 1];
        const float bx1 = boxes[r * 4 + 2];
        const float by1 = boxes[r * 4 + 3];
        const float w = bx1 - bx0 + 1.0f;
        const float hh = by1 - by0 + 1.0f;
        const float cx = bx0 + 0.5f * w;
        const float cy = by0 + 0.5f * hh;

        const float* reg = &sl[NUM_CLASSES + j * 4];
        const float dx = reg[0] * 0.1f;
        const float dy = reg[1] * 0.1f;
        const float dw = fminf(reg[2] * 0.2f, BBOX_XFORM_CLIP);
        const float dh = fminf(reg[3] * 0.2f, BBOX_XFORM_CLIP);

        const float pcx = dx * w + cx;
        const float pcy = dy * hh + cy;
        const float pw = expf(dw) * w;
        const float ph = expf(dh) * hh;

        float* orow = out + (size_t)r * ldo;
        orow[t] = keep ? p : 0.f;
        const int bo = (NUM_CLASSES - 1) + t * 4;
        orow[bo + 0] = keep ? (pcx - 0.5f * pw) : 0.f;
        orow[bo + 1] = keep ? (pcy - 0.5f * ph) : 0.f;
        orow[bo + 2] = keep ? (pcx + 0.5f * pw - 1.0f) : 0.f;
        orow[bo + 3] = keep ? (pcy + 0.5f * ph - 1.0f) : 0.f;
    }
}

// --------------------------- launch ---------------------------------------
extern "C" void kernel_launch(void* const* d_in, const int* in_sizes, int n_in,
                              void* d_out, int out_size) {
    const float* x      = (const float*)d_in[0];
    const float* boxes  = (const float*)d_in[1];
    const float* W6     = (const float*)d_in[2];
    const float* b6     = (const float*)d_in[3];
    const float* W7     = (const float*)d_in[4];
    const float* b7     = (const float*)d_in[5];
    const float* Wcls   = (const float*)d_in[6];
    const float* bcls   = (const float*)d_in[7];
    const float* Wbox   = (const float*)d_in[8];
    const float* bbox_b = (const float*)d_in[9];
    float* out = (float*)d_out;
    (void)n_in; (void)out_size;

    const int M  = in_sizes[1] / 4;       // 2000
    const int K1 = in_sizes[0] / M;       // 12544
    const int H  = in_sizes[3];           // 1024
    const int NC = in_sizes[7];           // 81
    const int OUTW = (NC - 1) * 5 + H;    // 1424

    __half *xh, *w6h, *w7h, *whh, *f6h, *f7h;
    float *part;
    cudaGetSymbolAddress((void**)&xh, g_xh);
    cudaGetSymbolAddress((void**)&w6h, g_w6h);
    cudaGetSymbolAddress((void**)&w7h, g_w7h);
    cudaGetSymbolAddress((void**)&whh, g_whh);
    cudaGetSymbolAddress((void**)&f6h, g_f6h);
    cudaGetSymbolAddress((void**)&f7h, g_f7h);
    cudaGetSymbolAddress((void**)&part, g_part);

    const int SMEM_BYTES = 3 * 16384;  // 48KB
    cudaFuncSetAttribute(hmma_gemm_f16,
                         cudaFuncAttributeMaxDynamicSharedMemorySize, SMEM_BYTES);

    // 1) mega prep: x -> fp16, all weights transposed fp16 (single grid)
    {
        const int nbW6 = (H / 32) * (K1 / 32);
        const int nbW7 = (H / 32) * (H / 32);
        const int nbWc = ((NC + 31) / 32) * (H / 32);
        const int nbWb = ((NC * 4 + 31) / 32) * (H / 32);
        const int nb = NBX + nbW6 + nbW7 + nbWc + nbWb;
        prep_kernel<<<nb, 256>>>(x, W6, W7, Wcls, Wbox,
                                 xh, w6h, w7h, whh, M, K1, H, NC);
    }

    const int MB = (M + 127) / 128;  // 16
    // 2) GEMM1 (split-K=2) + reduce -> f6 (out cols [400,1424)) + fp16 copy
    hmma_gemm_f16<<<dim3(H / 128, MB, 2), 256, SMEM_BYTES>>>(
        M, H, K1, K1 / 2, xh, w6h, part);
    reduce_epilogue<<<(M * H / 2 + 255) / 256, 256>>>(
        M, H, part, b6, 1, out + (NC - 1) * 5, OUTW, f6h, H);
    // 3) GEMM2 (split-K=2) + reduce -> f7 fp16
    hmma_gemm_f16<<<dim3(H / 128, MB, 2), 256, SMEM_BYTES>>>(
        M, H, H, H / 2, f6h, w7h, part);
    reduce_epilogue<<<(M * H / 2 + 255) / 256, 256>>>(
        M, H, part, b7, 1, nullptr, 0, f7h, H);
    // 4) head GEMM (split-K=2); reduce fused into postprocess
    hmma_gemm_f16<<<dim3(NHEAD / 128, MB, 2), 256, SMEM_BYTES>>>(
        M, NHEAD, H, H / 2, f7h, whh, part);
    // 5) postprocess (+head reduce + bias)
    postprocess_kernel<<<M, 128>>>(M, part, bcls, bbox_b, boxes, out, OUTW);
}

// round 15
// speedup vs baseline: 1.1490x; 1.1490x over previous
#include <cuda_runtime.h>
#include <cuda_fp16.h>
#include <cstdint>

// ---------------------------------------------------------------------------
// GeneralizedRCNNExtractModel via HMMA (mma.sync f16) GEMMs.
//   f6     = relu(x @ W6 + b6)            2000x12544 @ 12544x1024
//   f7     = relu(f6 @ W7 + b7)           2000x1024  @ 1024x1024
//   logits = f7 @ [Wcls|Wbox] + bias      2000x1024 @ 1024x405 (pad 512)
// R15: R12 GEMM config restored (best known: 128x128, 4 warps of 64x64,
// chunk 32, 2 CTAs/SM). GEMM1 is at the HMMA steady-state ceiling
// (~560 MACs/cyc/SM); this round compresses the tail: GEMM2 becomes
// split-K=1 with fused bias+relu+f16 epilogue (reduce kernel dropped,
// ~28MB partial traffic eliminated). 6 launches.
// ---------------------------------------------------------------------------

#define NUM_CLASSES 81
#define SCORE_THRESH 0.05f
#define BBOX_XFORM_CLIP 4.135166556742356f

#define RMAX 2000
#define KDIM 12544
#define HDIM 1024
#define NHEAD 512   // 405 used, padded

// --------------------------- device scratch -------------------------------
__device__ __half g_xh[RMAX * KDIM];     // fp16 x
__device__ __half g_w6h[HDIM * KDIM];    // W6^T fp16 [N][K]
__device__ __half g_w7h[HDIM * HDIM];    // W7^T fp16
__device__ __half g_whh[NHEAD * HDIM];   // [Wcls|Wbox]^T; rows 405..511 zero
__device__ __half g_f6h[RMAX * HDIM];
__device__ __half g_f7h[RMAX * HDIM];
__device__ float  g_part[2 * RMAX * HDIM];   // split-K partials

// --------------------------- PTX helpers ----------------------------------
__device__ __forceinline__ uint32_t smem_to_u32(const void* p) {
    uint32_t a;
    asm("{ .reg .u64 t; cvta.to.shared.u64 t, %1; cvt.u32.u64 %0, t; }"
        : "=r"(a) : "l"(p));
    return a;
}
__device__ __forceinline__ void cp_async16(uint32_t dst, const void* src, bool pred) {
    int sz = pred ? 16 : 0;
    asm volatile("cp.async.cg.shared.global [%0], [%1], 16, %2;"
                 :: "r"(dst), "l"(src), "r"(sz) : "memory");
}
#define CP_COMMIT() asm volatile("cp.async.commit_group;" ::: "memory")
#define CP_WAIT(N)  asm volatile("cp.async.wait_group %0;" :: "n"(N) : "memory")

__device__ __forceinline__ void ldsm_x4(uint32_t& r0, uint32_t& r1,
                                        uint32_t& r2, uint32_t& r3, uint32_t addr) {
    asm volatile("ldmatrix.sync.aligned.m8n8.x4.shared.b16 {%0,%1,%2,%3}, [%4];"
                 : "=r"(r0), "=r"(r1), "=r"(r2), "=r"(r3) : "r"(addr));
}
__device__ __forceinline__ void mma16816h(float* c, const uint32_t* a,
                                          uint32_t b0, uint32_t b1) {
    asm volatile(
        "mma.sync.aligned.m16n8k16.row.col.f32.f16.f16.f32 "
        "{%0,%1,%2,%3}, {%4,%5,%6,%7}, {%8,%9}, {%0,%1,%2,%3};"
        : "+f"(c[0]), "+f"(c[1]), "+f"(c[2]), "+f"(c[3])
        : "r"(a[0]), "r"(a[1]), "r"(a[2]), "r"(a[3]), "r"(b0), "r"(b1));
}

// swizzled smem offset for (row, 16B-chunk), 64B logical rows.
__device__ __forceinline__ uint32_t swoff(int row, int chunk) {
    return (uint32_t)(row * 64 + ((chunk ^ ((row >> 1) & 3)) << 4));
}

// --------------------------- mega prep kernel -----------------------------
#define NBX 1024

__device__ void transpose_half_job(const float* __restrict__ W, int K, int Nsrc,
                                   int ldT, int rowoff,
                                   __half* __restrict__ Th, int lb, int tid) {
    __shared__ float t[32][33];
    const int ntn = (Nsrc + 31) / 32;
    const int n0 = (lb % ntn) * 32;
    const int k0 = (lb / ntn) * 32;
    const int tx = tid & 31, ty = tid >> 5;  // 32 x 8
#pragma unroll
    for (int i = 0; i < 32; i += 8) {
        float v = 0.f;
        if (n0 + tx < Nsrc)
            v = W[(size_t)(k0 + ty + i) * Nsrc + n0 + tx];
        t[ty + i][tx] = v;
    }
    __syncthreads();
#pragma unroll
    for (int i = 0; i < 32; i += 8) {
        const int n = n0 + ty + i;
        if (n >= Nsrc) continue;
        Th[(size_t)(rowoff + n) * ldT + k0 + tx] = __float2half(t[tx][ty + i]);
    }
}

__global__ __launch_bounds__(256)
void prep_kernel(const float* __restrict__ x,
                 const float* __restrict__ W6,
                 const float* __restrict__ W7,
                 const float* __restrict__ Wcls,
                 const float* __restrict__ Wbox,
                 __half* __restrict__ xh,
                 __half* __restrict__ w6h,
                 __half* __restrict__ w7h,
                 __half* __restrict__ whh,
                 int M, int K1, int H, int NC) {
    const int tid = threadIdx.x;
    const int nbW6 = (H / 32) * (K1 / 32);
    const int nbW7 = (H / 32) * (H / 32);
    const int nbWc = ((NC + 31) / 32) * (H / 32);
    const int nbWb = ((NC * 4 + 31) / 32) * (H / 32);
    int b = blockIdx.x;

    if (b < NBX) {
        const size_t n4 = ((size_t)M * K1) / 4;
        size_t i = (size_t)b * 256 + tid;
        const size_t stride = (size_t)NBX * 256;
        const float4* X4 = reinterpret_cast<const float4*>(x);
        __half2* H2 = reinterpret_cast<__half2*>(xh);
        for (; i < n4; i += stride) {
            float4 v = X4[i];
            H2[i * 2 + 0] = __half2(__float2half(v.x), __float2half(v.y));
            H2[i * 2 + 1] = __half2(__float2half(v.z), __float2half(v.w));
        }
        return;
    }
    b -= NBX;
    if (b < nbW6) { transpose_half_job(W6, K1, H, K1, 0, w6h, b, tid); return; }
    b -= nbW6;
    if (b < nbW7) { transpose_half_job(W7, H, H, H, 0, w7h, b, tid); return; }
    b -= nbW7;
    if (b < nbWc) { transpose_half_job(Wcls, H, NC, H, 0, whh, b, tid); return; }
    b -= nbWc;
    if (b < nbWb) { transpose_half_job(Wbox, H, NC * 4, H, NC, whh, b, tid); return; }
}

// --------------------------- GEMM core macro body -------------------------
// Shared mainloop for both GEMM variants (R12 config): block 128x128,
// 4 warps of 64x64, chunk 32, stage A 8K | B 8K, 3-stage pipeline.

struct GemmCtx {
    uint32_t sbase;
    int lane, wid, bm, bn, wm, wn;
    uint32_t offT[4];
    size_t gofA[4], gofB[4];
    bool predA[4];
    uint32_t aFrag[4][2], bFrag[4][2];
};

__device__ __forceinline__ void gemm_init(GemmCtx& c, const char* smem,
                                          int M, int K, int kbase) {
    c.sbase = smem_to_u32(smem);
    const int tid = threadIdx.x;
    c.lane = tid & 31;
    c.wid = tid >> 5;
    c.bm = blockIdx.y * 128;
    c.bn = blockIdx.x * 128;
    c.wm = (c.wid & 1) * 64;
    c.wn = (c.wid >> 1) * 64;
#pragma unroll
    for (int i = 0; i < 4; ++i) {
        const int idx = tid + i * 128;
        const int row = idx >> 2, ch = idx & 3;
        c.offT[i] = swoff(row, ch);
        const int ra = (c.bm + row < M) ? (c.bm + row) : (M - 1);
        c.predA[i] = (c.bm + row < M);
        c.gofA[i] = (size_t)ra * K + kbase + ch * 8;
        c.gofB[i] = (size_t)(c.bn + row) * K + kbase + ch * 8;
    }
#pragma unroll
    for (int mt = 0; mt < 4; ++mt) {
        const int row = c.wm + mt * 16 + (c.lane & 15);
#pragma unroll
        for (int kc = 0; kc < 2; ++kc)
            c.aFrag[mt][kc] = swoff(row, (c.lane >> 4) + kc * 2);
    }
#pragma unroll
    for (int nt = 0; nt < 4; ++nt) {
        const int row = c.wn + nt * 16 + ((c.lane & 7) | ((c.lane >> 4) << 3));
#pragma unroll
        for (int kc = 0; kc < 2; ++kc)
            c.bFrag[nt][kc] = swoff(row, ((c.lane >> 3) & 1) + kc * 2);
    }
}

__device__ __forceinline__ void gemm_mainloop(const GemmCtx& c, int S,
                                              const __half* A, const __half* B,
                                              float acc[4][8][4]) {
    constexpr uint32_t STAGE = 16384u;
    constexpr int NSTAGE = 3;
#pragma unroll
    for (int mt = 0; mt < 4; ++mt)
#pragma unroll
        for (int nf = 0; nf < 8; ++nf)
#pragma unroll
            for (int k = 0; k < 4; ++k) acc[mt][nf][k] = 0.f;

    auto issue = [&](int step) {
        const size_t k0 = (size_t)step * 32;
        const uint32_t st = (uint32_t)(step % NSTAGE) * STAGE;
#pragma unroll
        for (int i = 0; i < 4; ++i) {
            cp_async16(c.sbase + st + c.offT[i],        A + c.gofA[i] + k0, c.predA[i]);
            cp_async16(c.sbase + st + 8192 + c.offT[i], B + c.gofB[i] + k0, true);
        }
        CP_COMMIT();
    };

    issue(0);
    if (S > 1) issue(1);

#pragma unroll 1
    for (int s = 0; s < S; ++s) {
        if (s + 1 < S) { CP_WAIT(1); } else { CP_WAIT(0); }
        __syncthreads();
        if (s + 2 < S) issue(s + 2);

        const uint32_t baseA = c.sbase + (uint32_t)(s % NSTAGE) * STAGE;
        const uint32_t baseB = baseA + 8192u;
#pragma unroll
        for (int kc = 0; kc < 2; ++kc) {
            uint32_t a[4][4];
#pragma unroll
            for (int mt = 0; mt < 4; ++mt)
                ldsm_x4(a[mt][0], a[mt][1], a[mt][2], a[mt][3],
                        baseA + c.aFrag[mt][kc]);
#pragma unroll
            for (int nt = 0; nt < 4; ++nt) {
                uint32_t b0, b1, b2, b3;
                ldsm_x4(b0, b1, b2, b3, baseB + c.bFrag[nt][kc]);
#pragma unroll
                for (int mt = 0; mt < 4; ++mt) {
                    mma16816h(acc[mt][nt * 2 + 0], a[mt], b0, b1);
                    mma16816h(acc[mt][nt * 2 + 1], a[mt], b2, b3);
                }
            }
        }
    }
}

// --------------------------- variant 1: raw partials (split-K) ------------
__global__ __launch_bounds__(128, 2)
void hmma_gemm_f16(int M, int N, int K, int Ksl,
                   const __half* __restrict__ A,
                   const __half* __restrict__ B,
                   float* __restrict__ Pout) {
    extern __shared__ char smem[];
    GemmCtx c;
    gemm_init(c, smem, M, K, blockIdx.z * Ksl);
    float acc[4][8][4];
    gemm_mainloop(c, Ksl / 32, A, B, acc);

    float* P = Pout + (size_t)blockIdx.z * M * N;
#pragma unroll
    for (int mt = 0; mt < 4; ++mt) {
#pragma unroll
        for (int nf = 0; nf < 8; ++nf) {
            const int col = c.bn + c.wn + nf * 8 + (c.lane & 3) * 2;
#pragma unroll
            for (int half = 0; half < 2; ++half) {
                const int row = c.bm + c.wm + mt * 16 + (c.lane >> 2) + half * 8;
                if (row >= M) continue;
                *reinterpret_cast<float2*>(&P[(size_t)row * N + col]) =
                    make_float2(acc[mt][nf][half * 2 + 0],
                                acc[mt][nf][half * 2 + 1]);
            }
        }
    }
}

// --------------------------- variant 2: fused epilogue (no split-K) -------
// v = acc + bias, relu, write f16 Oh (ldo).
__global__ __launch_bounds__(128, 2)
void hmma_gemm_f16_ep(int M, int N, int K,
                      const __half* __restrict__ A,
                      const __half* __restrict__ B,
                      const float* __restrict__ bias,
                      __half* __restrict__ Oh, int ldo) {
    extern __shared__ char smem[];
    GemmCtx c;
    gemm_init(c, smem, M, K, 0);
    float acc[4][8][4];
    gemm_mainloop(c, K / 32, A, B, acc);

#pragma unroll
    for (int mt = 0; mt < 4; ++mt) {
#pragma unroll
        for (int nf = 0; nf < 8; ++nf) {
            const int col = c.bn + c.wn + nf * 8 + (c.lane & 3) * 2;
            const float b0 = bias[col], b1 = bias[col + 1];
#pragma unroll
            for (int half = 0; half < 2; ++half) {
                const int row = c.bm + c.wm + mt * 16 + (c.lane >> 2) + half * 8;
                if (row >= M) continue;
                float v0 = fmaxf(acc[mt][nf][half * 2 + 0] + b0, 0.f);
                float v1 = fmaxf(acc[mt][nf][half * 2 + 1] + b1, 0.f);
                *reinterpret_cast<__half2*>(&Oh[(size_t)row * ldo + col]) =
                    __half2(__float2half(v0), __float2half(v1));
            }
        }
    }
}

// --------------------------- split-K reduce + epilogue --------------------
__global__ __launch_bounds__(256)
void reduce_epilogue(int M, int N,
                     const float* __restrict__ P,
                     const float* __restrict__ bias, int do_relu,
                     float* __restrict__ C, int ldc,
                     __half* __restrict__ Oh, int ldo) {
    const size_t i = (size_t)blockIdx.x * blockDim.x + threadIdx.x;
    const size_t n2 = (size_t)M * N / 2;
    if (i >= n2) return;
    const float2 p0 = reinterpret_cast<const float2*>(P)[i];
    const float2 p1 = reinterpret_cast<const float2*>(P + (size_t)M * N)[i];
    const int col = (int)((i * 2) % N);
    const int row = (int)((i * 2) / N);
    float v0 = p0.x + p1.x + bias[col];
    float v1 = p0.y + p1.y + bias[col + 1];
    if (do_relu) { v0 = fmaxf(v0, 0.f); v1 = fmaxf(v1, 0.f); }
    if (C)
        *reinterpret_cast<float2*>(&C[(size_t)row * ldc + col]) =
            make_float2(v0, v1);
    if (Oh)
        *reinterpret_cast<__half2*>(&Oh[(size_t)row * ldo + col]) =
            __half2(__float2half(v0), __float2half(v1));
}

// --------------------------- postprocess (+head reduce) -------------------
__global__ __launch_bounds__(128)
void postprocess_kernel(int M,
                        const float* __restrict__ P,   // [2][M][NHEAD]
                        const float* __restrict__ bcls,
                        const float* __restrict__ bbox_b,
                        const float* __restrict__ boxes,
                        float* __restrict__ out, int ldo) {
    const int r = blockIdx.x;
    const int t = threadIdx.x;
    __shared__ float sl[NUM_CLASSES * 5];  // 405
    __shared__ float smax, ssum;

    const float* p0 = P + (size_t)r * NHEAD;
    const float* p1 = P + (size_t)M * NHEAD + (size_t)r * NHEAD;
    for (int i = t; i < NUM_CLASSES * 5; i += 128) {
        const float bias = (i < NUM_CLASSES) ? bcls[i] : bbox_b[i - NUM_CLASSES];
        sl[i] = p0[i] + p1[i] + bias;
    }
    __syncthreads();

    if (t == 0) {
        float m = -1e30f;
        for (int i = 0; i < NUM_CLASSES; ++i) m = fmaxf(m, sl[i]);
        float s = 0.f;
        for (int i = 0; i < NUM_CLASSES; ++i) s += expf(sl[i] - m);
        smax = m;
        ssum = s;
    }
    __syncthreads();

    if (t < NUM_CLASSES - 1) {
        const int j = t + 1;
        const float p = expf(sl[j] - smax) / ssum;
        const bool keep = p > SCORE_THRESH;

        const float bx0 = boxes[r * 4 + 0];
        const float by0 = boxes[r * 4 + 1];
        const float bx1 = boxes[r * 4 + 2];
        const float by1 = boxes[r * 4 + 3];
        const float w = bx1 - bx0 + 1.0f;
        const float hh = by1 - by0 + 1.0f;
        const float cx = bx0 + 0.5f * w;
        const float cy = by0 + 0.5f * hh;

        const float* reg = &sl[NUM_CLASSES + j * 4];
        const float dx = reg[0] * 0.1f;
        const float dy = reg[1] * 0.1f;
        const float dw = fminf(reg[2] * 0.2f, BBOX_XFORM_CLIP);
        const float dh = fminf(reg[3] * 0.2f, BBOX_XFORM_CLIP);

        const float pcx = dx * w + cx;
        const float pcy = dy * hh + cy;
        const float pw = expf(dw) * w;
        const float ph = expf(dh) * hh;

        float* orow = out + (size_t)r * ldo;
        orow[t] = keep ? p : 0.f;
        const int bo = (NUM_CLASSES - 1) + t * 4;
        orow[bo + 0] = keep ? (pcx - 0.5f * pw) : 0.f;
        orow[bo + 1] = keep ? (pcy - 0.5f * ph) : 0.f;
        orow[bo + 2] = keep ? (pcx + 0.5f * pw - 1.0f) : 0.f;
        orow[bo + 3] = keep ? (pcy + 0.5f * ph - 1.0f) : 0.f;
    }
}

// --------------------------- launch ---------------------------------------
extern "C" void kernel_launch(void* const* d_in, const int* in_sizes, int n_in,
                              void* d_out, int out_size) {
    const float* x      = (const float*)d_in[0];
    const float* boxes  = (const float*)d_in[1];
    const float* W6     = (const float*)d_in[2];
    const float* b6     = (const float*)d_in[3];
    const float* W7     = (const float*)d_in[4];
    const float* b7     = (const float*)d_in[5];
    const float* Wcls   = (const float*)d_in[6];
    const float* bcls   = (const float*)d_in[7];
    const float* Wbox   = (const float*)d_in[8];
    const float* bbox_b = (const float*)d_in[9];
    float* out = (float*)d_out;
    (void)n_in; (void)out_size;

    const int M  = in_sizes[1] / 4;       // 2000
    const int K1 = in_sizes[0] / M;       // 12544
    const int H  = in_sizes[3];           // 1024
    const int NC = in_sizes[7];           // 81
    const int OUTW = (NC - 1) * 5 + H;    // 1424

    __half *xh, *w6h, *w7h, *whh, *f6h, *f7h;
    float *part;
    cudaGetSymbolAddress((void**)&xh, g_xh);
    cudaGetSymbolAddress((void**)&w6h, g_w6h);
    cudaGetSymbolAddress((void**)&w7h, g_w7h);
    cudaGetSymbolAddress((void**)&whh, g_whh);
    cudaGetSymbolAddress((void**)&f6h, g_f6h);
    cudaGetSymbolAddress((void**)&f7h, g_f7h);
    cudaGetSymbolAddress((void**)&part, g_part);

    const int SMEM_BYTES = 3 * 16384;  // 48KB
    cudaFuncSetAttribute(hmma_gemm_f16,
                         cudaFuncAttributeMaxDynamicSharedMemorySize, SMEM_BYTES);
    cudaFuncSetAttribute(hmma_gemm_f16_ep,
                         cudaFuncAttributeMaxDynamicSharedMemorySize, SMEM_BYTES);

    // 1) mega prep: x -> fp16, all weights transposed fp16 (single grid)
    {
        const int nbW6 = (H / 32) * (K1 / 32);
        const int nbW7 = (H / 32) * (H / 32);
        const int nbWc = ((NC + 31) / 32) * (H / 32);
        const int nbWb = ((NC * 4 + 31) / 32) * (H / 32);
        const int nb = NBX + nbW6 + nbW7 + nbWc + nbWb;
        prep_kernel<<<nb, 256>>>(x, W6, W7, Wcls, Wbox,
                                 xh, w6h, w7h, whh, M, K1, H, NC);
    }

    const int MB = (M + 127) / 128;  // 16
    // 2) GEMM1 (split-K=2) + reduce -> f6 (out cols [400,1424)) + fp16 copy
    hmma_gemm_f16<<<dim3(H / 128, MB, 2), 128, SMEM_BYTES>>>(
        M, H, K1, K1 / 2, xh, w6h, part);
    reduce_epilogue<<<(M * H / 2 + 255) / 256, 256>>>(
        M, H, part, b6, 1, out + (NC - 1) * 5, OUTW, f6h, H);
    // 3) GEMM2 (split-K=1, fused bias+relu+f16 epilogue) -> f7
    hmma_gemm_f16_ep<<<dim3(H / 128, MB, 1), 128, SMEM_BYTES>>>(
        M, H, H, f6h, w7h, b7, f7h, H);
    // 4) head GEMM (split-K=2); reduce fused into postprocess
    hmma_gemm_f16<<<dim3(NHEAD / 128, MB, 2), 128, SMEM_BYTES>>>(
        M, NHEAD, H, H / 2, f7h, whh, part);
    // 5) postprocess (+head reduce + bias)
    postprocess_kernel<<<M, 128>>>(M, part, bcls, bbox_b, boxes, out, OUTW);
}

// round 17
// speedup vs baseline: 1.1638x; 1.0129x over previous
#include <cuda_runtime.h>
#include <cuda_fp16.h>
#include <cstdint>

// ---------------------------------------------------------------------------
// GeneralizedRCNNExtractModel via HMMA (mma.sync f16) GEMMs.
//   f6     = relu(x @ W6 + b6)            2000x12544 @ 12544x1024
//   f7     = relu(f6 @ W7 + b7)           2000x1024  @ 1024x1024
//   logits = f7 @ [Wcls|Wbox] + bias      2000x1024 @ 1024x405 (pad 512)
// R17: R16 with the aliasing bug fixed — head bias lives in its own
// __device__ g_bhead (R16 packed it into g_part's tail, which GEMM1's
// split-K partials overwrite). GEMM1 unchanged (at HMMA ceiling);
// GEMM2 + head use the BM=64 fused-epilogue variant (block 64x128,
// 36KB smem, 2 CTAs/SM, split-K=1, grid 256/128 CTAs). 6 launches.
// ---------------------------------------------------------------------------

#define NUM_CLASSES 81
#define SCORE_THRESH 0.05f
#define BBOX_XFORM_CLIP 4.135166556742356f

#define RMAX 2000
#define KDIM 12544
#define HDIM 1024
#define NHEAD 512   // 405 used, padded

// --------------------------- device scratch -------------------------------
__device__ __half g_xh[RMAX * KDIM];     // fp16 x
__device__ __half g_w6h[HDIM * KDIM];    // W6^T fp16 [N][K]
__device__ __half g_w7h[HDIM * HDIM];    // W7^T fp16
__device__ __half g_whh[NHEAD * HDIM];   // [Wcls|Wbox]^T; rows 405..511 zero
__device__ __half g_f6h[RMAX * HDIM];
__device__ __half g_f7h[RMAX * HDIM];
__device__ float  g_logits[RMAX * NHEAD];
__device__ float  g_part[2 * RMAX * HDIM];   // split-K partials (GEMM1)
__device__ float  g_bhead[NHEAD];            // packed head bias (own buffer!)

// --------------------------- PTX helpers ----------------------------------
__device__ __forceinline__ uint32_t smem_to_u32(const void* p) {
    uint32_t a;
    asm("{ .reg .u64 t; cvta.to.shared.u64 t, %1; cvt.u32.u64 %0, t; }"
        : "=r"(a) : "l"(p));
    return a;
}
__device__ __forceinline__ void cp_async16(uint32_t dst, const void* src, bool pred) {
    int sz = pred ? 16 : 0;
    asm volatile("cp.async.cg.shared.global [%0], [%1], 16, %2;"
                 :: "r"(dst), "l"(src), "r"(sz) : "memory");
}
#define CP_COMMIT() asm volatile("cp.async.commit_group;" ::: "memory")
#define CP_WAIT(N)  asm volatile("cp.async.wait_group %0;" :: "n"(N) : "memory")

__device__ __forceinline__ void ldsm_x4(uint32_t& r0, uint32_t& r1,
                                        uint32_t& r2, uint32_t& r3, uint32_t addr) {
    asm volatile("ldmatrix.sync.aligned.m8n8.x4.shared.b16 {%0,%1,%2,%3}, [%4];"
                 : "=r"(r0), "=r"(r1), "=r"(r2), "=r"(r3) : "r"(addr));
}
__device__ __forceinline__ void mma16816h(float* c, const uint32_t* a,
                                          uint32_t b0, uint32_t b1) {
    asm volatile(
        "mma.sync.aligned.m16n8k16.row.col.f32.f16.f16.f32 "
        "{%0,%1,%2,%3}, {%4,%5,%6,%7}, {%8,%9}, {%0,%1,%2,%3};"
        : "+f"(c[0]), "+f"(c[1]), "+f"(c[2]), "+f"(c[3])
        : "r"(a[0]), "r"(a[1]), "r"(a[2]), "r"(a[3]), "r"(b0), "r"(b1));
}

// swizzled smem offset for (row, 16B-chunk), 64B logical rows.
__device__ __forceinline__ uint32_t swoff(int row, int chunk) {
    return (uint32_t)(row * 64 + ((chunk ^ ((row >> 1) & 3)) << 4));
}

// --------------------------- mega prep kernel -----------------------------
#define NBX 1024

__device__ void transpose_half_job(const float* __restrict__ W, int K, int Nsrc,
                                   int ldT, int rowoff,
                                   __half* __restrict__ Th, int lb, int tid) {
    __shared__ float t[32][33];
    const int ntn = (Nsrc + 31) / 32;
    const int n0 = (lb % ntn) * 32;
    const int k0 = (lb / ntn) * 32;
    const int tx = tid & 31, ty = tid >> 5;  // 32 x 8
#pragma unroll
    for (int i = 0; i < 32; i += 8) {
        float v = 0.f;
        if (n0 + tx < Nsrc)
            v = W[(size_t)(k0 + ty + i) * Nsrc + n0 + tx];
        t[ty + i][tx] = v;
    }
    __syncthreads();
#pragma unroll
    for (int i = 0; i < 32; i += 8) {
        const int n = n0 + ty + i;
        if (n >= Nsrc) continue;
        Th[(size_t)(rowoff + n) * ldT + k0 + tx] = __float2half(t[tx][ty + i]);
    }
}

__global__ __launch_bounds__(256)
void prep_kernel(const float* __restrict__ x,
                 const float* __restrict__ W6,
                 const float* __restrict__ W7,
                 const float* __restrict__ Wcls,
                 const float* __restrict__ Wbox,
                 const float* __restrict__ bcls,
                 const float* __restrict__ bbox_b,
                 __half* __restrict__ xh,
                 __half* __restrict__ w6h,
                 __half* __restrict__ w7h,
                 __half* __restrict__ whh,
                 float* __restrict__ bhead,
                 int M, int K1, int H, int NC) {
    const int tid = threadIdx.x;
    const int nbW6 = (H / 32) * (K1 / 32);
    const int nbW7 = (H / 32) * (H / 32);
    const int nbWc = ((NC + 31) / 32) * (H / 32);
    const int nbWb = ((NC * 4 + 31) / 32) * (H / 32);
    int b = blockIdx.x;

    if (b < NBX) {
        // block 0 additionally packs the head bias (512 values, 256 thr x2)
        if (b == 0) {
#pragma unroll
            for (int i = 0; i < 2; ++i) {
                const int t = tid + i * 256;
                float v = 0.f;
                if (t < NC) v = bcls[t];
                else if (t < NC * 5) v = bbox_b[t - NC];
                bhead[t] = v;
            }
        }
        const size_t n4 = ((size_t)M * K1) / 4;
        size_t i = (size_t)b * 256 + tid;
        const size_t stride = (size_t)NBX * 256;
        const float4* X4 = reinterpret_cast<const float4*>(x);
        __half2* H2 = reinterpret_cast<__half2*>(xh);
        for (; i < n4; i += stride) {
            float4 v = X4[i];
            H2[i * 2 + 0] = __half2(__float2half(v.x), __float2half(v.y));
            H2[i * 2 + 1] = __half2(__float2half(v.z), __float2half(v.w));
        }
        return;
    }
    b -= NBX;
    if (b < nbW6) { transpose_half_job(W6, K1, H, K1, 0, w6h, b, tid); return; }
    b -= nbW6;
    if (b < nbW7) { transpose_half_job(W7, H, H, H, 0, w7h, b, tid); return; }
    b -= nbW7;
    if (b < nbWc) { transpose_half_job(Wcls, H, NC, H, 0, whh, b, tid); return; }
    b -= nbWc;
    if (b < nbWb) { transpose_half_job(Wbox, H, NC * 4, H, NC, whh, b, tid); return; }
}

// --------------------------- GEMM1: raw partials (split-K, BM128) ---------
// Block 128x128, 4 warps of 64x64, chunk 32, stage A 8K | B 8K, 3 stages.
__global__ __launch_bounds__(128, 2)
void hmma_gemm_f16(int M, int N, int K, int Ksl,
                   const __half* __restrict__ A,
                   const __half* __restrict__ B,
                   float* __restrict__ Pout) {
    extern __shared__ char smem[];
    const uint32_t sbase = smem_to_u32(smem);
    const int tid = threadIdx.x, lane = tid & 31, wid = tid >> 5;
    const int bm = blockIdx.y * 128, bn = blockIdx.x * 128;
    const int wm = (wid & 1) * 64, wn = (wid >> 1) * 64;
    const int kbase = blockIdx.z * Ksl;

    constexpr uint32_t STAGE = 16384u;
    constexpr int NSTAGE = 3;

    uint32_t offT[4];
    size_t gofA[4], gofB[4];
    bool predA[4];
#pragma unroll
    for (int i = 0; i < 4; ++i) {
        const int idx = tid + i * 128;
        const int row = idx >> 2, ch = idx & 3;
        offT[i] = swoff(row, ch);
        const int ra = (bm + row < M) ? (bm + row) : (M - 1);
        predA[i] = (bm + row < M);
        gofA[i] = (size_t)ra * K + kbase + ch * 8;
        gofB[i] = (size_t)(bn + row) * K + kbase + ch * 8;
    }

    uint32_t aFrag[4][2], bFrag[4][2];
#pragma unroll
    for (int mt = 0; mt < 4; ++mt) {
        const int row = wm + mt * 16 + (lane & 15);
#pragma unroll
        for (int kc = 0; kc < 2; ++kc)
            aFrag[mt][kc] = swoff(row, (lane >> 4) + kc * 2);
    }
#pragma unroll
    for (int nt = 0; nt < 4; ++nt) {
        const int row = wn + nt * 16 + ((lane & 7) | ((lane >> 4) << 3));
#pragma unroll
        for (int kc = 0; kc < 2; ++kc)
            bFrag[nt][kc] = swoff(row, ((lane >> 3) & 1) + kc * 2);
    }

    float acc[4][8][4];
#pragma unroll
    for (int mt = 0; mt < 4; ++mt)
#pragma unroll
        for (int nf = 0; nf < 8; ++nf)
#pragma unroll
            for (int k = 0; k < 4; ++k) acc[mt][nf][k] = 0.f;

    const int S = Ksl / 32;

    auto issue = [&](int step) {
        const size_t k0 = (size_t)step * 32;
        const uint32_t st = (uint32_t)(step % NSTAGE) * STAGE;
#pragma unroll
        for (int i = 0; i < 4; ++i) {
            cp_async16(sbase + st + offT[i],        A + gofA[i] + k0, predA[i]);
            cp_async16(sbase + st + 8192 + offT[i], B + gofB[i] + k0, true);
        }
        CP_COMMIT();
    };

    issue(0);
    if (S > 1) issue(1);

#pragma unroll 1
    for (int s = 0; s < S; ++s) {
        if (s + 1 < S) { CP_WAIT(1); } else { CP_WAIT(0); }
        __syncthreads();
        if (s + 2 < S) issue(s + 2);

        const uint32_t baseA = sbase + (uint32_t)(s % NSTAGE) * STAGE;
        const uint32_t baseB = baseA + 8192u;
#pragma unroll
        for (int kc = 0; kc < 2; ++kc) {
            uint32_t a[4][4];
#pragma unroll
            for (int mt = 0; mt < 4; ++mt)
                ldsm_x4(a[mt][0], a[mt][1], a[mt][2], a[mt][3],
                        baseA + aFrag[mt][kc]);
#pragma unroll
            for (int nt = 0; nt < 4; ++nt) {
                uint32_t b0, b1, b2, b3;
                ldsm_x4(b0, b1, b2, b3, baseB + bFrag[nt][kc]);
#pragma unroll
                for (int mt = 0; mt < 4; ++mt) {
                    mma16816h(acc[mt][nt * 2 + 0], a[mt], b0, b1);
                    mma16816h(acc[mt][nt * 2 + 1], a[mt], b2, b3);
                }
            }
        }
    }

    float* P = Pout + (size_t)blockIdx.z * M * N;
#pragma unroll
    for (int mt = 0; mt < 4; ++mt) {
#pragma unroll
        for (int nf = 0; nf < 8; ++nf) {
            const int col = bn + wn + nf * 8 + (lane & 3) * 2;
#pragma unroll
            for (int half = 0; half < 2; ++half) {
                const int row = bm + wm + mt * 16 + (lane >> 2) + half * 8;
                if (row >= M) continue;
                *reinterpret_cast<float2*>(&P[(size_t)row * N + col]) =
                    make_float2(acc[mt][nf][half * 2 + 0],
                                acc[mt][nf][half * 2 + 1]);
            }
        }
    }
}

// --------------------------- BM64 fused-epilogue GEMM ---------------------
// Block 64x128, 4 warps of 32x64, chunk 32, stage A 4K | B 8K (12KB),
// 3 stages = 36KB, 2 CTAs/SM, split-K=1.
// Epilogue: v = acc + bias (+relu); writes f16 Oh and/or f32 Cf.
__global__ __launch_bounds__(128, 2)
void hmma_gemm_f16_ep64(int M, int N, int K,
                        const __half* __restrict__ A,
                        const __half* __restrict__ B,
                        const float* __restrict__ bias, int do_relu,
                        __half* __restrict__ Oh, int ldo,
                        float* __restrict__ Cf, int ldc) {
    extern __shared__ char smem[];
    const uint32_t sbase = smem_to_u32(smem);
    const int tid = threadIdx.x, lane = tid & 31, wid = tid >> 5;
    const int bm = blockIdx.y * 64, bn = blockIdx.x * 128;
    const int wm = (wid & 1) * 32, wn = (wid >> 1) * 64;

    constexpr uint32_t STAGE = 12288u;   // A 4K | B 8K
    constexpr int NSTAGE = 3;

    // A tile: 64 rows x 4 chunks = 256 slots -> 2 iters.
    uint32_t offA[2];
    size_t gofA[2];
    bool predA[2];
#pragma unroll
    for (int i = 0; i < 2; ++i) {
        const int idx = tid + i * 128;
        const int row = idx >> 2, ch = idx & 3;
        offA[i] = swoff(row, ch);
        const int ra = (bm + row < M) ? (bm + row) : (M - 1);
        predA[i] = (bm + row < M);
        gofA[i] = (size_t)ra * K + ch * 8;
    }
    // B tile: 128 rows x 4 chunks = 512 slots -> 4 iters.
    uint32_t offB[4];
    size_t gofB[4];
#pragma unroll
    for (int i = 0; i < 4; ++i) {
        const int idx = tid + i * 128;
        const int row = idx >> 2, ch = idx & 3;
        offB[i] = swoff(row, ch);
        gofB[i] = (size_t)(bn + row) * K + ch * 8;
    }

    uint32_t aFrag[2][2], bFrag[4][2];
#pragma unroll
    for (int mt = 0; mt < 2; ++mt) {
        const int row = wm + mt * 16 + (lane & 15);
#pragma unroll
        for (int kc = 0; kc < 2; ++kc)
            aFrag[mt][kc] = swoff(row, (lane >> 4) + kc * 2);
    }
#pragma unroll
    for (int nt = 0; nt < 4; ++nt) {
        const int row = wn + nt * 16 + ((lane & 7) | ((lane >> 4) << 3));
#pragma unroll
        for (int kc = 0; kc < 2; ++kc)
            bFrag[nt][kc] = swoff(row, ((lane >> 3) & 1) + kc * 2);
    }

    float acc[2][8][4];   // 64 regs
#pragma unroll
    for (int mt = 0; mt < 2; ++mt)
#pragma unroll
        for (int nf = 0; nf < 8; ++nf)
#pragma unroll
            for (int k = 0; k < 4; ++k) acc[mt][nf][k] = 0.f;

    const int S = K / 32;

    auto issue = [&](int step) {
        const size_t k0 = (size_t)step * 32;
        const uint32_t st = (uint32_t)(step % NSTAGE) * STAGE;
#pragma unroll
        for (int i = 0; i < 2; ++i)
            cp_async16(sbase + st + offA[i], A + gofA[i] + k0, predA[i]);
#pragma unroll
        for (int i = 0; i < 4; ++i)
            cp_async16(sbase + st + 4096 + offB[i], B + gofB[i] + k0, true);
        CP_COMMIT();
    };

    issue(0);
    if (S > 1) issue(1);

#pragma unroll 1
    for (int s = 0; s < S; ++s) {
        if (s + 1 < S) { CP_WAIT(1); } else { CP_WAIT(0); }
        __syncthreads();
        if (s + 2 < S) issue(s + 2);

        const uint32_t baseA = sbase + (uint32_t)(s % NSTAGE) * STAGE;
        const uint32_t baseB = baseA + 4096u;
#pragma unroll
        for (int kc = 0; kc < 2; ++kc) {
            uint32_t a[2][4];
            ldsm_x4(a[0][0], a[0][1], a[0][2], a[0][3], baseA + aFrag[0][kc]);
            ldsm_x4(a[1][0], a[1][1], a[1][2], a[1][3], baseA + aFrag[1][kc]);
#pragma unroll
            for (int nt = 0; nt < 4; ++nt) {
                uint32_t b0, b1, b2, b3;
                ldsm_x4(b0, b1, b2, b3, baseB + bFrag[nt][kc]);
                mma16816h(acc[0][nt * 2 + 0], a[0], b0, b1);
                mma16816h(acc[0][nt * 2 + 1], a[0], b2, b3);
                mma16816h(acc[1][nt * 2 + 0], a[1], b0, b1);
                mma16816h(acc[1][nt * 2 + 1], a[1], b2, b3);
            }
        }
    }

#pragma unroll
    for (int mt = 0; mt < 2; ++mt) {
#pragma unroll
        for (int nf = 0; nf < 8; ++nf) {
            const int col = bn + wn + nf * 8 + (lane & 3) * 2;
            const float b0 = bias[col], b1 = bias[col + 1];
#pragma unroll
            for (int half = 0; half < 2; ++half) {
                const int row = bm + wm + mt * 16 + (lane >> 2) + half * 8;
                if (row >= M) continue;
                float v0 = acc[mt][nf][half * 2 + 0] + b0;
                float v1 = acc[mt][nf][half * 2 + 1] + b1;
                if (do_relu) { v0 = fmaxf(v0, 0.f); v1 = fmaxf(v1, 0.f); }
                if (Oh)
                    *reinterpret_cast<__half2*>(&Oh[(size_t)row * ldo + col]) =
                        __half2(__float2half(v0), __float2half(v1));
                if (Cf)
                    *reinterpret_cast<float2*>(&Cf[(size_t)row * ldc + col]) =
                        make_float2(v0, v1);
            }
        }
    }
}

// --------------------------- split-K reduce + epilogue (GEMM1) ------------
__global__ __launch_bounds__(256)
void reduce_epilogue(int M, int N,
                     const float* __restrict__ P,
                     const float* __restrict__ bias, int do_relu,
                     float* __restrict__ C, int ldc,
                     __half* __restrict__ Oh, int ldo) {
    const size_t i = (size_t)blockIdx.x * blockDim.x + threadIdx.x;
    const size_t n2 = (size_t)M * N / 2;
    if (i >= n2) return;
    const float2 p0 = reinterpret_cast<const float2*>(P)[i];
    const float2 p1 = reinterpret_cast<const float2*>(P + (size_t)M * N)[i];
    const int col = (int)((i * 2) % N);
    const int row = (int)((i * 2) / N);
    float v0 = p0.x + p1.x + bias[col];
    float v1 = p0.y + p1.y + bias[col + 1];
    if (do_relu) { v0 = fmaxf(v0, 0.f); v1 = fmaxf(v1, 0.f); }
    if (C)
        *reinterpret_cast<float2*>(&C[(size_t)row * ldc + col]) =
            make_float2(v0, v1);
    if (Oh)
        *reinterpret_cast<__half2*>(&Oh[(size_t)row * ldo + col]) =
            __half2(__float2half(v0), __float2half(v1));
}

// --------------------------- postprocess ----------------------------------
__global__ __launch_bounds__(128)
void postprocess_kernel(const float* __restrict__ logits, int ldl,
                        const float* __restrict__ boxes,
                        float* __restrict__ out, int ldo) {
    const int r = blockIdx.x;
    const int t = threadIdx.x;
    __shared__ float sl[NUM_CLASSES * 5];  // 405
    __shared__ float smax, ssum;

    for (int i = t; i < NUM_CLASSES * 5; i += 128)
        sl[i] = logits[(size_t)r * ldl + i];
    __syncthreads();

    if (t == 0) {
        float m = -1e30f;
        for (int i = 0; i < NUM_CLASSES; ++i) m = fmaxf(m, sl[i]);
        float s = 0.f;
        for (int i = 0; i < NUM_CLASSES; ++i) s += expf(sl[i] - m);
        smax = m;
        ssum = s;
    }
    __syncthreads();

    if (t < NUM_CLASSES - 1) {
        const int j = t + 1;
        const float p = expf(sl[j] - smax) / ssum;
        const bool keep = p > SCORE_THRESH;

        const float bx0 = boxes[r * 4 + 0];
        const float by0 = boxes[r * 4 + 1];
        const float bx1 = boxes[r * 4 + 2];
        const float by1 = boxes[r * 4 + 3];
        const float w = bx1 - bx0 + 1.0f;
        const float hh = by1 - by0 + 1.0f;
        const float cx = bx0 + 0.5f * w;
        const float cy = by0 + 0.5f * hh;

        const float* reg = &sl[NUM_CLASSES + j * 4];
        const float dx = reg[0] * 0.1f;
        const float dy = reg[1] * 0.1f;
        const float dw = fminf(reg[2] * 0.2f, BBOX_XFORM_CLIP);
        const float dh = fminf(reg[3] * 0.2f, BBOX_XFORM_CLIP);

        const float pcx = dx * w + cx;
        const float pcy = dy * hh + cy;
        const float pw = expf(dw) * w;
        const float ph = expf(dh) * hh;

        float* orow = out + (size_t)r * ldo;
        orow[t] = keep ? p : 0.f;
        const int bo = (NUM_CLASSES - 1) + t * 4;
        orow[bo + 0] = keep ? (pcx - 0.5f * pw) : 0.f;
        orow[bo + 1] = keep ? (pcy - 0.5f * ph) : 0.f;
        orow[bo + 2] = keep ? (pcx + 0.5f * pw - 1.0f) : 0.f;
        orow[bo + 3] = keep ? (pcy + 0.5f * ph - 1.0f) : 0.f;
    }
}

// --------------------------- launch ---------------------------------------
extern "C" void kernel_launch(void* const* d_in, const int* in_sizes, int n_in,
                              void* d_out, int out_size) {
    const float* x      = (const float*)d_in[0];
    const float* boxes  = (const float*)d_in[1];
    const float* W6     = (const float*)d_in[2];
    const float* b6     = (const float*)d_in[3];
    const float* W7     = (const float*)d_in[4];
    const float* b7     = (const float*)d_in[5];
    const float* Wcls   = (const float*)d_in[6];
    const float* bcls   = (const float*)d_in[7];
    const float* Wbox   = (const float*)d_in[8];
    const float* bbox_b = (const float*)d_in[9];
    float* out = (float*)d_out;
    (void)n_in; (void)out_size;

    const int M  = in_sizes[1] / 4;       // 2000
    const int K1 = in_sizes[0] / M;       // 12544
    const int H  = in_sizes[3];           // 1024
    const int NC = in_sizes[7];           // 81
    const int OUTW = (NC - 1) * 5 + H;    // 1424

    __half *xh, *w6h, *w7h, *whh, *f6h, *f7h;
    float *part, *logits, *bhead;
    cudaGetSymbolAddress((void**)&xh, g_xh);
    cudaGetSymbolAddress((void**)&w6h, g_w6h);
    cudaGetSymbolAddress((void**)&w7h, g_w7h);
    cudaGetSymbolAddress((void**)&whh, g_whh);
    cudaGetSymbolAddress((void**)&f6h, g_f6h);
    cudaGetSymbolAddress((void**)&f7h, g_f7h);
    cudaGetSymbolAddress((void**)&part, g_part);
    cudaGetSymbolAddress((void**)&logits, g_logits);
    cudaGetSymbolAddress((void**)&bhead, g_bhead);

    const int SMEM_128 = 3 * 16384;  // 48KB
    const int SMEM_64  = 3 * 12288;  // 36KB
    cudaFuncSetAttribute(hmma_gemm_f16,
                         cudaFuncAttributeMaxDynamicSharedMemorySize, SMEM_128);
    cudaFuncSetAttribute(hmma_gemm_f16_ep64,
                         cudaFuncAttributeMaxDynamicSharedMemorySize, SMEM_64);

    // 1) mega prep (+ head bias packing in block 0)
    {
        const int nbW6 = (H / 32) * (K1 / 32);
        const int nbW7 = (H / 32) * (H / 32);
        const int nbWc = ((NC + 31) / 32) * (H / 32);
        const int nbWb = ((NC * 4 + 31) / 32) * (H / 32);
        const int nb = NBX + nbW6 + nbW7 + nbWc + nbWb;
        prep_kernel<<<nb, 256>>>(x, W6, W7, Wcls, Wbox, bcls, bbox_b,
                                 xh, w6h, w7h, whh, bhead, M, K1, H, NC);
    }

    const int MB128 = (M + 127) / 128;  // 16
    const int MB64  = (M + 63) / 64;    // 32
    // 2) GEMM1 (split-K=2) + reduce -> f6 (out cols [400,1424)) + fp16 copy
    hmma_gemm_f16<<<dim3(H / 128, MB128, 2), 128, SMEM_128>>>(
        M, H, K1, K1 / 2, xh, w6h, part);
    reduce_epilogue<<<(M * H / 2 + 255) / 256, 256>>>(
        M, H, part, b6, 1, out + (NC - 1) * 5, OUTW, f6h, H);
    // 3) GEMM2 (BM64 fused, split-K=1, 256 CTAs) -> f7 fp16
    hmma_gemm_f16_ep64<<<dim3(H / 128, MB64), 128, SMEM_64>>>(
        M, H, H, f6h, w7h, b7, 1, f7h, H, nullptr, 0);
    // 4) head GEMM (BM64 fused) -> logits f32
    hmma_gemm_f16_ep64<<<dim3(NHEAD / 128, MB64), 128, SMEM_64>>>(
        M, NHEAD, H, f7h, whh, bhead, 0, nullptr, 0, logits, NHEAD);
    // 5) postprocess
    postprocess_kernel<<<M, 128>>>(logits, NHEAD, boxes, out, OUTW);
}